// round 13
// baseline (speedup 1.0000x reference)
#include <cuda_runtime.h>
#include <cstdint>
#include <math.h>
#include <mma.h>

using namespace nvcuda;

// Problem dims (fixed)
#define S_ 256
#define B_ 256
#define I_ 256
#define H_ 512
#define G_ 2048            // 4*H
#define SB_ (S_*B_)        // 65536
#define BH_ (B_*H_)        // 131072
#define LBH_ (2*BH_)       // 262144
#define OUT_OFF_H (SB_*H_) // 33554432
#define OUT_OFF_C (OUT_OFF_H + LBH_)

// ---------------------------------------------------------------------------
// Device scratch (no allocations allowed)
// ---------------------------------------------------------------------------
__device__ float g_X[(size_t)SB_ * G_];     // 512 MB: gate-interleaved X preacts
__device__ float g_H0[(size_t)SB_ * H_];    // 128 MB: unmasked layer-0 h outputs
__device__ float g_hstate[2][LBH_];         // ping-pong h state
__device__ float g_cstate[LBH_];            // c state
// Gate-interleaved (row = hcol*4 + gate) weight copies + combined biases
__device__ float g_Wihp0[(size_t)G_ * I_];
__device__ float g_Whhp0[(size_t)G_ * H_];     // tf32-hi part
__device__ float g_Whhp0lo[(size_t)G_ * H_];   // tf32 residual
__device__ float g_Wihp1[(size_t)G_ * H_];
__device__ float g_Whhp1[(size_t)G_ * H_];     // tf32-hi part
__device__ float g_Whhp1lo[(size_t)G_ * H_];   // tf32 residual
__device__ float g_bp0[G_];
__device__ float g_bp1[G_];

__device__ __forceinline__ float sig_(float x)  { return 1.0f / (1.0f + __expf(-x)); }
__device__ __forceinline__ float tanh_(float x) { return 2.0f / (1.0f + __expf(-2.0f*x)) - 1.0f; }

// Round fp32 -> tf32 (RNA). Standard PTX (sm_80+), fine on compute_103.
__device__ __forceinline__ float tf32r(float x) {
    uint32_t r;
    asm("cvt.rna.tf32.f32 %0, %1;" : "=r"(r) : "f"(x));
    return __uint_as_float(r);
}

// ---------------------------------------------------------------------------
// One-time permutes: dst row r' = hcol*4+gate  <-  src row gate*512+hcol
// For W_hh (sel 1,3) also produce tf32 hi/lo split.
// ---------------------------------------------------------------------------
__global__ void permute_w_kernel(int dst_sel, const float* __restrict__ src, int K) {
    const int K4 = K >> 2;
    const int total = G_ * K4;
    int i = blockIdx.x * 256 + threadIdx.x;
    if (i >= total) return;
    int r = i / K4, k4 = i - r * K4;
    int c = r >> 2, g = r & 3;
    float4 v = ((const float4*)src)[(size_t)(g * H_ + c) * K4 + k4];
    if (dst_sel == 1 || dst_sel == 3) {
        float4 hi, lo;
        hi.x = tf32r(v.x); lo.x = tf32r(v.x - hi.x);
        hi.y = tf32r(v.y); lo.y = tf32r(v.y - hi.y);
        hi.z = tf32r(v.z); lo.z = tf32r(v.z - hi.z);
        hi.w = tf32r(v.w); lo.w = tf32r(v.w - hi.w);
        float* dh = (dst_sel == 1) ? g_Whhp0   : g_Whhp1;
        float* dl = (dst_sel == 1) ? g_Whhp0lo : g_Whhp1lo;
        ((float4*)dh)[i] = hi;
        ((float4*)dl)[i] = lo;
    } else {
        float* dst = (dst_sel == 0) ? g_Wihp0 : g_Wihp1;
        ((float4*)dst)[i] = v;
    }
}

__global__ void permute_b_kernel(int dst_sel, const float* __restrict__ b1,
                                 const float* __restrict__ b2) {
    float* dst = dst_sel ? g_bp1 : g_bp0;
    int r = blockIdx.x * 256 + threadIdx.x;
    if (r >= G_) return;
    int c = r >> 2, g = r & 3;
    dst[r] = b1[g * H_ + c] + b2[g * H_ + c];
}

// ---------------------------------------------------------------------------
// Input-projection GEMM (fp32, unchanged from the passing R2 kernel):
// X[m,n] = A[m,:]·Wp[n,:] + bp[n]; M=65536, N=2048, K=256/512.
// ---------------------------------------------------------------------------
__global__ void __launch_bounds__(256) gemm_bias_kernel(
    const float* __restrict__ Aext, int use_gH0, int wsel, int K)
{
    __shared__ float As[8][128];
    __shared__ float Ws[8][132];

    const float* __restrict__ A = use_gH0 ? g_H0 : Aext;
    const float* __restrict__ W = wsel ? g_Wihp1 : g_Wihp0;
    const float* __restrict__ bp = wsel ? g_bp1 : g_bp0;

    const int bn = blockIdx.x, bm = blockIdx.y;
    const int tid = threadIdx.x;
    const int row = tid >> 1, kq = (tid & 1) << 2;
    const int ty = tid >> 4, tx = tid & 15;

    float acc[8][8];
    #pragma unroll
    for (int i = 0; i < 8; i++)
        #pragma unroll
        for (int j = 0; j < 8; j++) acc[i][j] = 0.0f;

    const float* Ap = A + (size_t)(bm*128 + row)*K + kq;
    const float* Wp = W + (size_t)(bn*128 + row)*K + kq;

    for (int k0 = 0; k0 < K; k0 += 8) {
        float4 a = *(const float4*)(Ap + k0);
        float4 w = *(const float4*)(Wp + k0);
        __syncthreads();
        As[kq+0][row] = a.x; As[kq+1][row] = a.y; As[kq+2][row] = a.z; As[kq+3][row] = a.w;
        Ws[kq+0][row] = w.x; Ws[kq+1][row] = w.y; Ws[kq+2][row] = w.z; Ws[kq+3][row] = w.w;
        __syncthreads();
        #pragma unroll
        for (int k = 0; k < 8; k++) {
            float af[8], wf[8];
            *(float4*)(af)   = *(const float4*)&As[k][ty*8];
            *(float4*)(af+4) = *(const float4*)&As[k][ty*8+4];
            *(float4*)(wf)   = *(const float4*)&Ws[k][tx*8];
            *(float4*)(wf+4) = *(const float4*)&Ws[k][tx*8+4];
            #pragma unroll
            for (int i = 0; i < 8; i++)
                #pragma unroll
                for (int j = 0; j < 8; j++)
                    acc[i][j] = fmaf(af[i], wf[j], acc[i][j]);
        }
    }
    #pragma unroll
    for (int j = 0; j < 8; j++) {
        const int n = bn*128 + tx*8 + j;
        const float bias = bp[n];
        #pragma unroll
        for (int i = 0; i < 8; i++)
            g_X[(size_t)(bm*128 + ty*8 + i)*G_ + n] = acc[i][j] + bias;
    }
}

// ---------------------------------------------------------------------------
// Recurrent step via wmma tf32 (legacy HMMA path — standard sm_80+ PTX):
// gates = Xpre + h @ Whhp^T (3xTF32 compensated), fused LSTM cell + mask.
// Grid (32 Ntiles, 4 Mtiles) = 128 CTAs, 256 threads (8 warps).
// Block tile 64(batch) x 64(gate-cols); warp tile 32x16 (2 M-strips of 16).
// ---------------------------------------------------------------------------
#define LDC 72   // smem C tile leading dim (72*4B = 288B, 32B-aligned rows)

__global__ void __launch_bounds__(256) lstm_step_wmma(
    int t, int layer, const float* __restrict__ done, float* __restrict__ out)
{
    __shared__ float Cs[64 * LDC];

    const int tid  = threadIdx.x;
    const int wid  = tid >> 5;
    const int wm   = wid & 1;          // 0..1: M strip pair (32 rows)
    const int wn   = wid >> 1;         // 0..3: N strip (16 cols)
    const int bx   = blockIdx.x;       // 0..31: gate-col tile (64 cols)
    const int by   = blockIdx.y;       // 0..3 : batch tile (64 rows)

    const float* __restrict__ Wh = layer ? g_Whhp1   : g_Whhp0;
    const float* __restrict__ Wl = layer ? g_Whhp1lo : g_Whhp0lo;
    const float* __restrict__ Xpre = g_X + (size_t)t * B_ * G_;
    const int p = t & 1;
    const float* __restrict__ hin = g_hstate[p] + layer*BH_;
    float* __restrict__ hout      = g_hstate[p ^ 1] + layer*BH_;
    float* __restrict__ cst       = g_cstate + layer*BH_;
    float* __restrict__ hum       = (layer == 0) ? (g_H0 + (size_t)t*BH_)
                                                 : (out  + (size_t)t*BH_);

    const int b0 = by*64 + wm*32;      // first batch row of this warp's strips
    const int n0 = bx*64 + wn*16;      // first gate-col of this warp

    wmma::fragment<wmma::accumulator, 16, 16, 8, float> acc[2];
    wmma::fill_fragment(acc[0], 0.0f);
    wmma::fill_fragment(acc[1], 0.0f);

    const float* Ab  = hin + (size_t)b0 * H_;
    const float* Bhb = Wh  + (size_t)n0 * H_;
    const float* Blb = Wl  + (size_t)n0 * H_;

    #pragma unroll 4
    for (int k0 = 0; k0 < H_; k0 += 8) {
        wmma::fragment<wmma::matrix_b, 16, 16, 8, wmma::precision::tf32, wmma::col_major> bh, bl;
        wmma::load_matrix_sync(bh, Bhb + k0, H_);
        wmma::load_matrix_sync(bl, Blb + k0, H_);

        #pragma unroll
        for (int s = 0; s < 2; s++) {
            wmma::fragment<wmma::matrix_a, 16, 16, 8, wmma::precision::tf32, wmma::row_major> ar, ahi, alo;
            wmma::load_matrix_sync(ar, Ab + (size_t)(s*16)*H_ + k0, H_);
            #pragma unroll
            for (int e = 0; e < ar.num_elements; e++) {
                float v  = ar.x[e];
                float hi = wmma::__float_to_tf32(v);
                ahi.x[e] = hi;
                alo.x[e] = wmma::__float_to_tf32(v - hi);
            }
            wmma::mma_sync(acc[s], ahi, bh, acc[s]);
            wmma::mma_sync(acc[s], alo, bh, acc[s]);
            wmma::mma_sync(acc[s], ahi, bl, acc[s]);
        }
    }

    // Stage accumulators to smem: Cs[row(batch-local 0..63)][col(gate-local 0..63)]
    #pragma unroll
    for (int s = 0; s < 2; s++)
        wmma::store_matrix_sync(&Cs[(wm*32 + s*16)*LDC + wn*16], acc[s], LDC,
                                wmma::mem_row_major);
    __syncthreads();

    // Fused epilogue: 1024 hcol-quads / 256 threads = 4 per thread.
    #pragma unroll
    for (int j = 0; j < 4; j++) {
        const int q    = j*256 + tid;        // 0..1023
        const int brow = q >> 4;             // 0..63  batch-local
        const int hl   = q & 15;             // 0..15  hcol-local
        const int b    = by*64 + brow;       // global batch row
        const int hcol = bx*16 + hl;         // global hidden col

        float4 gq = *(const float4*)&Cs[brow*LDC + hl*4];
        float4 xq = *(const float4*)&Xpre[(size_t)b*G_ + bx*64 + hl*4];

        const float gi = gq.x + xq.x;
        const float gf = gq.y + xq.y;
        const float gg = gq.z + xq.z;
        const float go = gq.w + xq.w;

        const float co = cst[(size_t)b*H_ + hcol];
        const float cv = sig_(gf)*co + sig_(gi)*tanh_(gg);
        const float hv = sig_(go)*tanh_(cv);
        const float m  = 1.0f - done[t*B_ + b];

        hum [(size_t)b*H_ + hcol] = hv;
        hout[(size_t)b*H_ + hcol] = hv * m;
        cst [(size_t)b*H_ + hcol] = cv * m;
    }
}

// ---------------------------------------------------------------------------
__global__ void init_states_kernel(const float* __restrict__ h0,
                                   const float* __restrict__ c0)
{
    int i = blockIdx.x*blockDim.x + threadIdx.x;
    if (i < LBH_) {
        g_hstate[0][i] = h0[i];
        g_hstate[1][i] = 0.0f;
        g_cstate[i]    = c0[i];
    }
}

__global__ void finalize_kernel(float* __restrict__ out)
{
    int i = blockIdx.x*blockDim.x + threadIdx.x;
    if (i < LBH_) {
        out[OUT_OFF_H + i] = g_hstate[0][i];  // after 256 steps, final parity = 0
        out[OUT_OFF_C + i] = g_cstate[i];
    }
}

// ---------------------------------------------------------------------------
extern "C" void kernel_launch(void* const* d_in, const int* in_sizes, int n_in,
                              void* d_out, int out_size)
{
    const float* x    = (const float*)d_in[0];
    const float* h0   = (const float*)d_in[1];
    const float* c0   = (const float*)d_in[2];
    const float* done = (const float*)d_in[3];
    const float* Wih0 = (const float*)d_in[4];
    const float* Whh0 = (const float*)d_in[5];
    const float* bih0 = (const float*)d_in[6];
    const float* bhh0 = (const float*)d_in[7];
    const float* Wih1 = (const float*)d_in[8];
    const float* Whh1 = (const float*)d_in[9];
    const float* bih1 = (const float*)d_in[10];
    const float* bhh1 = (const float*)d_in[11];
    float* out = (float*)d_out;

    init_states_kernel<<<(LBH_ + 255)/256, 256>>>(h0, c0);

    // Permute weights/biases to gate-interleaved layout (+ hi/lo split for W_hh)
    permute_w_kernel<<<(G_*(I_/4) + 255)/256, 256>>>(0, Wih0, I_);
    permute_w_kernel<<<(G_*(H_/4) + 255)/256, 256>>>(1, Whh0, H_);
    permute_w_kernel<<<(G_*(H_/4) + 255)/256, 256>>>(2, Wih1, H_);
    permute_w_kernel<<<(G_*(H_/4) + 255)/256, 256>>>(3, Whh1, H_);
    permute_b_kernel<<<(G_ + 255)/256, 256>>>(0, bih0, bhh0);
    permute_b_kernel<<<(G_ + 255)/256, 256>>>(1, bih1, bhh1);

    dim3 ggrid(G_/128, SB_/128);   // (16, 512)
    dim3 sgrid(32, 4);             // (gate-col tiles, batch tiles) = 128 CTAs

    // Layer 0
    gemm_bias_kernel<<<ggrid, 256>>>(x, 0, 0, I_);
    for (int t = 0; t < S_; t++)
        lstm_step_wmma<<<sgrid, 256>>>(t, 0, done, out);

    // Layer 1 (input = unmasked layer-0 outputs)
    gemm_bias_kernel<<<ggrid, 256>>>(nullptr, 1, 1, H_);
    for (int t = 0; t < S_; t++)
        lstm_step_wmma<<<sgrid, 256>>>(t, 1, done, out);

    finalize_kernel<<<(LBH_ + 255)/256, 256>>>(out);
}

// round 16
// speedup vs baseline: 1.2950x; 1.2950x over previous
#include <cuda_runtime.h>
#include <cstdint>
#include <math.h>
#include <mma.h>

using namespace nvcuda;

// Problem dims (fixed)
#define S_ 256
#define B_ 256
#define I_ 256
#define H_ 512
#define G_ 2048            // 4*H
#define SB_ (S_*B_)        // 65536
#define BH_ (B_*H_)        // 131072
#define LBH_ (2*BH_)       // 262144
#define OUT_OFF_H (SB_*H_) // 33554432
#define OUT_OFF_C (OUT_OFF_H + LBH_)

// wmma tiling constants
#define KC    32           // K-chunk
#define LDAB  40           // smem leading dim for A/B tiles (multiple of 8)
#define MATF  (64*LDAB)    // floats per 64-row tile = 2560
#define STAGEF (4*MATF)    // Ah,Al,Bh,Bl per stage = 10240 floats
#define SMEM_BYTES (2*STAGEF*4)   // 81920 B
#define LDC   72           // smem C staging leading dim (multiple of 8)

// ---------------------------------------------------------------------------
// Device scratch (no allocations allowed)
// ---------------------------------------------------------------------------
__device__ float g_X[(size_t)SB_ * G_];     // gate-interleaved X preacts
__device__ float g_H0[(size_t)SB_ * H_];    // unmasked layer-0 h outputs
__device__ float g_hstate[2][LBH_];         // ping-pong h state
__device__ float g_cstate[LBH_];            // c state
// Gate-interleaved (row = hcol*4 + gate) weights, tf32 hi/lo split
__device__ float g_Wihp0[(size_t)G_ * I_];
__device__ float g_Wihp0lo[(size_t)G_ * I_];
__device__ float g_Whhp0[(size_t)G_ * H_];
__device__ float g_Whhp0lo[(size_t)G_ * H_];
__device__ float g_Wihp1[(size_t)G_ * H_];
__device__ float g_Wihp1lo[(size_t)G_ * H_];
__device__ float g_Whhp1[(size_t)G_ * H_];
__device__ float g_Whhp1lo[(size_t)G_ * H_];
__device__ float g_bp0[G_];
__device__ float g_bp1[G_];

__device__ __forceinline__ float sig_(float x)  { return 1.0f / (1.0f + __expf(-x)); }
__device__ __forceinline__ float tanh_(float x) { return 2.0f / (1.0f + __expf(-2.0f*x)) - 1.0f; }

// Round fp32 -> tf32 (RNA). Standard PTX (sm_80+).
__device__ __forceinline__ float tf32r(float x) {
    uint32_t r;
    asm("cvt.rna.tf32.f32 %0, %1;" : "=r"(r) : "f"(x));
    return __uint_as_float(r);
}

// ---------------------------------------------------------------------------
// One-time permutes: dst row r' = hcol*4+gate  <-  src row gate*512+hcol.
// ALL weights get tf32 hi/lo split.
// ---------------------------------------------------------------------------
__global__ void permute_w_kernel(int dst_sel, const float* __restrict__ src, int K) {
    const int K4 = K >> 2;
    const int total = G_ * K4;
    int i = blockIdx.x * 256 + threadIdx.x;
    if (i >= total) return;
    int r = i / K4, k4 = i - r * K4;
    int c = r >> 2, g = r & 3;
    float4 v = ((const float4*)src)[(size_t)(g * H_ + c) * K4 + k4];
    float4 hi, lo;
    hi.x = tf32r(v.x); lo.x = tf32r(v.x - hi.x);
    hi.y = tf32r(v.y); lo.y = tf32r(v.y - hi.y);
    hi.z = tf32r(v.z); lo.z = tf32r(v.z - hi.z);
    hi.w = tf32r(v.w); lo.w = tf32r(v.w - hi.w);
    float *dh, *dl;
    if      (dst_sel == 0) { dh = g_Wihp0; dl = g_Wihp0lo; }
    else if (dst_sel == 1) { dh = g_Whhp0; dl = g_Whhp0lo; }
    else if (dst_sel == 2) { dh = g_Wihp1; dl = g_Wihp1lo; }
    else                   { dh = g_Whhp1; dl = g_Whhp1lo; }
    ((float4*)dh)[i] = hi;
    ((float4*)dl)[i] = lo;
}

__global__ void permute_b_kernel(int dst_sel, const float* __restrict__ b1,
                                 const float* __restrict__ b2) {
    float* dst = dst_sel ? g_bp1 : g_bp0;
    int r = blockIdx.x * 256 + threadIdx.x;
    if (r >= G_) return;
    int c = r >> 2, g = r & 3;
    dst[r] = b1[g * H_ + c] + b2[g * H_ + c];
}

// ---------------------------------------------------------------------------
// Shared mainloop helpers (64x64 block tile, smem-staged, 3xTF32)
// ---------------------------------------------------------------------------
struct Pref { float4 a[2], bh[2], bl[2]; };

__device__ __forceinline__ void load_chunk(
    Pref& P, int tid,
    const float* __restrict__ Ab, const float* __restrict__ Bhb,
    const float* __restrict__ Blb, int k0, int ldg)
{
    #pragma unroll
    for (int i = 0; i < 2; i++) {
        const int row = (tid >> 3) + i*32, q = tid & 7;
        const size_t off = (size_t)row * ldg + k0 + q*4;
        P.a[i]  = *(const float4*)(Ab  + off);
        P.bh[i] = *(const float4*)(Bhb + off);
        P.bl[i] = *(const float4*)(Blb + off);
    }
}

__device__ __forceinline__ void store_chunk(const Pref& P, int tid, float* stage)
{
    float* Ah = stage;
    float* Al = stage +   MATF;
    float* Bh = stage + 2*MATF;
    float* Bl = stage + 3*MATF;
    #pragma unroll
    for (int i = 0; i < 2; i++) {
        const int row = (tid >> 3) + i*32, q = tid & 7;
        float4 v = P.a[i], hi, lo;
        hi.x = tf32r(v.x); lo.x = tf32r(v.x - hi.x);
        hi.y = tf32r(v.y); lo.y = tf32r(v.y - hi.y);
        hi.z = tf32r(v.z); lo.z = tf32r(v.z - hi.z);
        hi.w = tf32r(v.w); lo.w = tf32r(v.w - hi.w);
        *(float4*)(Ah + row*LDAB + q*4) = hi;
        *(float4*)(Al + row*LDAB + q*4) = lo;
        *(float4*)(Bh + row*LDAB + q*4) = P.bh[i];
        *(float4*)(Bl + row*LDAB + q*4) = P.bl[i];
    }
}

using FragA = wmma::fragment<wmma::matrix_a, 16, 16, 8, wmma::precision::tf32, wmma::row_major>;
using FragB = wmma::fragment<wmma::matrix_b, 16, 16, 8, wmma::precision::tf32, wmma::col_major>;
using FragC = wmma::fragment<wmma::accumulator, 16, 16, 8, float>;

// Compute one KC-chunk from a stage: warp (wm,wn), acc[2] = two 16-row strips
__device__ __forceinline__ void compute_chunk(
    FragC acc[2], const float* stage, int wm, int wn)
{
    const float* Ah = stage;
    const float* Al = stage +   MATF;
    const float* Bh = stage + 2*MATF;
    const float* Bl = stage + 3*MATF;
    #pragma unroll
    for (int kst = 0; kst < KC/8; kst++) {
        FragB bh, bl;
        wmma::load_matrix_sync(bh, Bh + (wn*16)*LDAB + kst*8, LDAB);
        wmma::load_matrix_sync(bl, Bl + (wn*16)*LDAB + kst*8, LDAB);
        #pragma unroll
        for (int s = 0; s < 2; s++) {
            FragA ahi, alo;
            wmma::load_matrix_sync(ahi, Ah + (wm*32 + s*16)*LDAB + kst*8, LDAB);
            wmma::load_matrix_sync(alo, Al + (wm*32 + s*16)*LDAB + kst*8, LDAB);
            wmma::mma_sync(acc[s], ahi, bh, acc[s]);
            wmma::mma_sync(acc[s], alo, bh, acc[s]);
            wmma::mma_sync(acc[s], ahi, bl, acc[s]);
        }
    }
}

// ---------------------------------------------------------------------------
// Input-projection GEMM (3xTF32 wmma): X[m,n] = A[m,:]·Wp[n,:] + bp[n]
// Grid (G/64=32, M/64). Block 64x64, 8 warps.
// ---------------------------------------------------------------------------
__global__ void __launch_bounds__(256) gemm3x_wmma(
    const float* __restrict__ Aext, int use_gH0, int wsel, int K)
{
    extern __shared__ float sm[];
    const int tid = threadIdx.x;
    const int wid = tid >> 5;
    const int wm = wid & 1, wn = wid >> 1;
    const int bx = blockIdx.x, by = blockIdx.y;

    const float* __restrict__ A  = use_gH0 ? g_H0 : Aext;
    const float* __restrict__ Wh = wsel ? g_Wihp1   : g_Wihp0;
    const float* __restrict__ Wl = wsel ? g_Wihp1lo : g_Wihp0lo;
    const float* __restrict__ bp = wsel ? g_bp1 : g_bp0;

    const float* Ab  = A  + (size_t)(by*64) * K;
    const float* Bhb = Wh + (size_t)(bx*64) * K;
    const float* Blb = Wl + (size_t)(bx*64) * K;

    FragC acc[2];
    wmma::fill_fragment(acc[0], 0.0f);
    wmma::fill_fragment(acc[1], 0.0f);

    const int nch = K / KC;
    Pref P;
    load_chunk(P, tid, Ab, Bhb, Blb, 0, K);
    store_chunk(P, tid, sm);
    __syncthreads();

    for (int ch = 0; ch < nch; ch++) {
        if (ch + 1 < nch) load_chunk(P, tid, Ab, Bhb, Blb, (ch+1)*KC, K);
        compute_chunk(acc, sm + (ch & 1)*STAGEF, wm, wn);
        if (ch + 1 < nch) store_chunk(P, tid, sm + ((ch+1) & 1)*STAGEF);
        __syncthreads();
    }

    // Stage C and write with bias
    float* Cs = sm;
    #pragma unroll
    for (int s = 0; s < 2; s++)
        wmma::store_matrix_sync(&Cs[(wm*32 + s*16)*LDC + wn*16], acc[s], LDC,
                                wmma::mem_row_major);
    __syncthreads();

    #pragma unroll
    for (int j = 0; j < 4; j++) {
        const int q = j*256 + tid;           // 0..1023 float4 slots
        const int brow = q >> 4, c4 = q & 15;
        const int n = bx*64 + c4*4;
        float4 c = *(const float4*)&Cs[brow*LDC + c4*4];
        float4 b = *(const float4*)&bp[n];
        c.x += b.x; c.y += b.y; c.z += b.z; c.w += b.w;
        *(float4*)&g_X[(size_t)(by*64 + brow)*G_ + n] = c;
    }
}

// ---------------------------------------------------------------------------
// Recurrent step (3xTF32 wmma, smem-staged): gates = Xpre + h @ Whhp^T,
// fused LSTM cell + done-mask. Grid (32, 4) = 128 CTAs, 8 warps.
// ---------------------------------------------------------------------------
__global__ void __launch_bounds__(256) lstm_step_wmma(
    int t, int layer, const float* __restrict__ done, float* __restrict__ out)
{
    extern __shared__ float sm[];
    const int tid = threadIdx.x;
    const int wid = tid >> 5;
    const int wm = wid & 1, wn = wid >> 1;
    const int bx = blockIdx.x, by = blockIdx.y;

    const float* __restrict__ Wh = layer ? g_Whhp1   : g_Whhp0;
    const float* __restrict__ Wl = layer ? g_Whhp1lo : g_Whhp0lo;
    const float* __restrict__ Xpre = g_X + (size_t)t * B_ * G_;
    const int p = t & 1;
    const float* __restrict__ hin = g_hstate[p] + layer*BH_;
    float* __restrict__ hout      = g_hstate[p ^ 1] + layer*BH_;
    float* __restrict__ cst       = g_cstate + layer*BH_;
    float* __restrict__ hum       = (layer == 0) ? (g_H0 + (size_t)t*BH_)
                                                 : (out  + (size_t)t*BH_);

    const float* Ab  = hin + (size_t)(by*64) * H_;
    const float* Bhb = Wh  + (size_t)(bx*64) * H_;
    const float* Blb = Wl  + (size_t)(bx*64) * H_;

    FragC acc[2];
    wmma::fill_fragment(acc[0], 0.0f);
    wmma::fill_fragment(acc[1], 0.0f);

    Pref P;
    load_chunk(P, tid, Ab, Bhb, Blb, 0, H_);
    store_chunk(P, tid, sm);
    __syncthreads();

    #pragma unroll 1
    for (int ch = 0; ch < H_/KC; ch++) {
        if (ch + 1 < H_/KC) load_chunk(P, tid, Ab, Bhb, Blb, (ch+1)*KC, H_);
        compute_chunk(acc, sm + (ch & 1)*STAGEF, wm, wn);
        if (ch + 1 < H_/KC) store_chunk(P, tid, sm + ((ch+1) & 1)*STAGEF);
        __syncthreads();
    }

    // Stage C, then fused epilogue
    float* Cs = sm;
    #pragma unroll
    for (int s = 0; s < 2; s++)
        wmma::store_matrix_sync(&Cs[(wm*32 + s*16)*LDC + wn*16], acc[s], LDC,
                                wmma::mem_row_major);
    __syncthreads();

    // 64 rows x 16 hcols: 1024 hcol-quads / 256 threads = 4 per thread
    #pragma unroll
    for (int j = 0; j < 4; j++) {
        const int q    = j*256 + tid;
        const int brow = q >> 4;             // batch-local 0..63
        const int hl   = q & 15;             // hcol-local 0..15
        const int b    = by*64 + brow;
        const int hcol = bx*16 + hl;

        float4 gq = *(const float4*)&Cs[brow*LDC + hl*4];
        float4 xq = *(const float4*)&Xpre[(size_t)b*G_ + bx*64 + hl*4];

        const float gi = gq.x + xq.x;
        const float gf = gq.y + xq.y;
        const float gg = gq.z + xq.z;
        const float go = gq.w + xq.w;

        const float co = cst[(size_t)b*H_ + hcol];
        const float cv = sig_(gf)*co + sig_(gi)*tanh_(gg);
        const float hv = sig_(go)*tanh_(cv);
        const float m  = 1.0f - done[t*B_ + b];

        hum [(size_t)b*H_ + hcol] = hv;
        hout[(size_t)b*H_ + hcol] = hv * m;
        cst [(size_t)b*H_ + hcol] = cv * m;
    }
}

// ---------------------------------------------------------------------------
__global__ void init_states_kernel(const float* __restrict__ h0,
                                   const float* __restrict__ c0)
{
    int i = blockIdx.x*blockDim.x + threadIdx.x;
    if (i < LBH_) {
        g_hstate[0][i] = h0[i];
        g_hstate[1][i] = 0.0f;
        g_cstate[i]    = c0[i];
    }
}

__global__ void finalize_kernel(float* __restrict__ out)
{
    int i = blockIdx.x*blockDim.x + threadIdx.x;
    if (i < LBH_) {
        out[OUT_OFF_H + i] = g_hstate[0][i];  // after 256 steps, final parity = 0
        out[OUT_OFF_C + i] = g_cstate[i];
    }
}

// ---------------------------------------------------------------------------
extern "C" void kernel_launch(void* const* d_in, const int* in_sizes, int n_in,
                              void* d_out, int out_size)
{
    const float* x    = (const float*)d_in[0];
    const float* h0   = (const float*)d_in[1];
    const float* c0   = (const float*)d_in[2];
    const float* done = (const float*)d_in[3];
    const float* Wih0 = (const float*)d_in[4];
    const float* Whh0 = (const float*)d_in[5];
    const float* bih0 = (const float*)d_in[6];
    const float* bhh0 = (const float*)d_in[7];
    const float* Wih1 = (const float*)d_in[8];
    const float* Whh1 = (const float*)d_in[9];
    const float* bih1 = (const float*)d_in[10];
    const float* bhh1 = (const float*)d_in[11];
    float* out = (float*)d_out;

    cudaFuncSetAttribute(lstm_step_wmma,
                         cudaFuncAttributeMaxDynamicSharedMemorySize, SMEM_BYTES);
    cudaFuncSetAttribute(gemm3x_wmma,
                         cudaFuncAttributeMaxDynamicSharedMemorySize, SMEM_BYTES);

    init_states_kernel<<<(LBH_ + 255)/256, 256>>>(h0, c0);

    // Permute weights/biases (gate-interleaved + tf32 hi/lo split)
    permute_w_kernel<<<(G_*(I_/4) + 255)/256, 256>>>(0, Wih0, I_);
    permute_w_kernel<<<(G_*(H_/4) + 255)/256, 256>>>(1, Whh0, H_);
    permute_w_kernel<<<(G_*(H_/4) + 255)/256, 256>>>(2, Wih1, H_);
    permute_w_kernel<<<(G_*(H_/4) + 255)/256, 256>>>(3, Whh1, H_);
    permute_b_kernel<<<(G_ + 255)/256, 256>>>(0, bih0, bhh0);
    permute_b_kernel<<<(G_ + 255)/256, 256>>>(1, bih1, bhh1);

    dim3 ggrid(G_/64, SB_/64);     // (32, 1024)
    dim3 sgrid(G_/64, B_/64);      // (32, 4) = 128 CTAs

    // Layer 0
    gemm3x_wmma<<<ggrid, 256, SMEM_BYTES>>>(x, 0, 0, I_);
    for (int t = 0; t < S_; t++)
        lstm_step_wmma<<<sgrid, 256, SMEM_BYTES>>>(t, 0, done, out);

    // Layer 1 (input = unmasked layer-0 outputs)
    gemm3x_wmma<<<ggrid, 256, SMEM_BYTES>>>(nullptr, 1, 1, H_);
    for (int t = 0; t < S_; t++)
        lstm_step_wmma<<<sgrid, 256, SMEM_BYTES>>>(t, 1, done, out);

    finalize_kernel<<<(LBH_ + 255)/256, 256>>>(out);
}